// round 5
// baseline (speedup 1.0000x reference)
#include <cuda_runtime.h>

#define TTOK 3136
#define DM 512

// Scratch (device globals — no allocation allowed)
__device__ float g_q[TTOK * DM];
__device__ float g_k[TTOK * DM];
__device__ float g_v[TTOK * DM];
__device__ float g_ao[TTOK * DM];

// ---------------------------------------------------------------------------
// Packed f32x2 helpers (FFMA2 path on sm_103a)
// ---------------------------------------------------------------------------
typedef unsigned long long u64t;

__device__ __forceinline__ u64t dup2(float x) {
    u64t r; asm("mov.b64 %0,{%1,%1};" : "=l"(r) : "f"(x)); return r;
}
__device__ __forceinline__ u64t ffma2(u64t a, u64t b, u64t c) {
    u64t d; asm("fma.rn.f32x2 %0,%1,%2,%3;" : "=l"(d) : "l"(a), "l"(b), "l"(c));
    return d;
}
__device__ __forceinline__ u64t mul2(u64t a, u64t b) {
    u64t d; asm("mul.rn.f32x2 %0,%1,%2;" : "=l"(d) : "l"(a), "l"(b));
    return d;
}
__device__ __forceinline__ float2 upk(u64t v) {
    float2 f; asm("mov.b64 {%0,%1},%2;" : "=f"(f.x), "=f"(f.y) : "l"(v));
    return f;
}
// Bank swizzle: flip bit2 (4 floats) when bit5 set -> conflict-free 8-lane x
// 8-float B-operand reads.
__device__ __forceinline__ int swz(int c) { return c ^ ((c & 32) >> 3); }

// ---------------------------------------------------------------------------
// GEMM: out[3136, 512] = (A1 (+A2)) @ W[512,512] + bias
// BM=128, BN=64, BK=16; 128 threads; 8x8 microtile, f32x2, double-buffered.
// ---------------------------------------------------------------------------
#define AS_ST 132
#define BS_ST 68

__device__ __forceinline__ void gemm_body(
    const float* __restrict__ A1, const float* __restrict__ A2,
    const float* __restrict__ W, const float* __restrict__ bias,
    float* __restrict__ out, int m0, int n0)
{
    __shared__ float As[2][16][AS_ST];   // A^T tile: As[k][m], m=128 wide
    __shared__ float Bs[2][16][BS_ST];   // Bs[k][n], n=64 wide, swizzled

    const int tid = threadIdx.x;
    const int tx = tid & 7;              // n cols tx*8..+7
    const int ty = tid >> 3;             // m rows ty*8..+7 (0..15)
    const int sA = swz(tx * 8), sB = swz(tx * 8 + 4);

    float4 pa[4]; float4 pb[2];

    // prefetch global tile (k0) into registers
    #define G_LOAD(k0)                                                        \
        {                                                                     \
            _Pragma("unroll")                                                 \
            for (int it = 0; it < 4; it++) {                                  \
                int i = tid + it * 128; int r = i >> 2, c4 = i & 3;           \
                float4 a = make_float4(0.f, 0.f, 0.f, 0.f);                   \
                if (m0 + r < TTOK) {                                          \
                    a = *(const float4*)(A1 + (size_t)(m0 + r) * DM + (k0) + c4 * 4); \
                    if (A2) {                                                 \
                        float4 p = *(const float4*)(A2 + (size_t)(m0 + r) * DM + (k0) + c4 * 4); \
                        a.x += p.x; a.y += p.y; a.z += p.z; a.w += p.w;       \
                    }                                                         \
                }                                                             \
                pa[it] = a;                                                   \
            }                                                                 \
            _Pragma("unroll")                                                 \
            for (int it = 0; it < 2; it++) {                                  \
                int i = tid + it * 128; int r = i >> 4, c4 = i & 15;          \
                pb[it] = *(const float4*)(W + (size_t)((k0) + r) * DM + n0 + c4 * 4); \
            }                                                                 \
        }

    #define S_STORE(b)                                                       \
        {                                                                    \
            _Pragma("unroll")                                                \
            for (int it = 0; it < 4; it++) {                                 \
                int i = tid + it * 128; int r = i >> 2, c4 = i & 3;          \
                As[b][c4 * 4 + 0][r] = pa[it].x;                             \
                As[b][c4 * 4 + 1][r] = pa[it].y;                             \
                As[b][c4 * 4 + 2][r] = pa[it].z;                             \
                As[b][c4 * 4 + 3][r] = pa[it].w;                             \
            }                                                                \
            _Pragma("unroll")                                                \
            for (int it = 0; it < 2; it++) {                                 \
                int i = tid + it * 128; int r = i >> 4, c4 = i & 15;         \
                *(float4*)&Bs[b][r][swz(c4 * 4)] = pb[it];                   \
            }                                                                \
        }

    u64t acc[8][4];
    #pragma unroll
    for (int i = 0; i < 8; i++)
        #pragma unroll
        for (int jp = 0; jp < 4; jp++) acc[i][jp] = 0ULL;

    G_LOAD(0);
    S_STORE(0);
    __syncthreads();

    int buf = 0;
    for (int k0 = 16;; k0 += 16) {
        const bool more = (k0 < DM);
        if (more) G_LOAD(k0);

        #pragma unroll
        for (int kk = 0; kk < 16; kk++) {
            float4 a0 = *(float4*)&As[buf][kk][ty * 8];
            float4 a1 = *(float4*)&As[buf][kk][ty * 8 + 4];
            ulonglong2 q0v = *(ulonglong2*)&Bs[buf][kk][sA];
            ulonglong2 q1v = *(ulonglong2*)&Bs[buf][kk][sB];
            u64t bp[4] = {q0v.x, q0v.y, q1v.x, q1v.y};
            float av[8] = {a0.x, a0.y, a0.z, a0.w, a1.x, a1.y, a1.z, a1.w};
            #pragma unroll
            for (int i = 0; i < 8; i++) {
                u64t ad = dup2(av[i]);
                #pragma unroll
                for (int jp = 0; jp < 4; jp++)
                    acc[i][jp] = ffma2(ad, bp[jp], acc[i][jp]);
            }
        }
        if (!more) break;
        S_STORE(buf ^ 1);
        __syncthreads();
        buf ^= 1;
    }

    float4 bA = *(const float4*)&bias[n0 + tx * 8];
    float4 bB = *(const float4*)&bias[n0 + tx * 8 + 4];
    #pragma unroll
    for (int i = 0; i < 8; i++) {
        int m = m0 + ty * 8 + i;
        if (m < TTOK) {
            float2 r0 = upk(acc[i][0]), r1 = upk(acc[i][1]);
            float2 r2 = upk(acc[i][2]), r3 = upk(acc[i][3]);
            float4 o0 = make_float4(r0.x + bA.x, r0.y + bA.y, r1.x + bA.z, r1.y + bA.w);
            float4 o1 = make_float4(r2.x + bB.x, r2.y + bB.y, r3.x + bB.z, r3.y + bB.w);
            *(float4*)&out[(size_t)m * DM + n0 + tx * 8]     = o0;
            *(float4*)&out[(size_t)m * DM + n0 + tx * 8 + 4] = o1;
        }
    }
    #undef G_LOAD
    #undef S_STORE
}

__global__ __launch_bounds__(128, 3) void gemm512_kernel(
    const float* __restrict__ A1, const float* __restrict__ A2,
    const float* __restrict__ W, const float* __restrict__ bias,
    float* __restrict__ out)
{
    gemm_body(A1, A2, W, bias, out, blockIdx.y * 128, blockIdx.x * 64);
}

__global__ __launch_bounds__(128, 3) void gemm_qkv_kernel(
    const float* __restrict__ xq, const float* __restrict__ xk,
    const float* __restrict__ pos,
    const float* __restrict__ Wq, const float* __restrict__ bq,
    const float* __restrict__ Wk, const float* __restrict__ bk,
    const float* __restrict__ Wv, const float* __restrict__ bv,
    float* __restrict__ oq, float* __restrict__ ok, float* __restrict__ ov)
{
    const float *A1, *A2, *W, *bias; float* out;
    if (blockIdx.z == 0)      { A1 = xq; A2 = pos;     W = Wq; bias = bq; out = oq; }
    else if (blockIdx.z == 1) { A1 = xk; A2 = pos;     W = Wk; bias = bk; out = ok; }
    else                      { A1 = xk; A2 = nullptr; W = Wv; bias = bv; out = ov; }
    gemm_body(A1, A2, W, bias, out, blockIdx.y * 128, blockIdx.x * 64);
}

// ---------------------------------------------------------------------------
// Block-diagonal flash attention: BQ=128, BKV=64, 128 threads, 8x8 microtile,
// f32x2 FMA, swizzled K/V operands, exp2-based online softmax.
// Grid: (28, 8). 28 = sum ceil(ch_i*196/128) for channels [2,4,6,4].
// ---------------------------------------------------------------------------
#define QT_ST 132
#define KV_ST 68
#define ATTN_SMEM_FLOATS (2 * 64 * QT_ST + 2 * 64 * KV_ST)

__global__ __launch_bounds__(128, 2) void attn_kernel(
    const float* __restrict__ gq, const float* __restrict__ gk,
    const float* __restrict__ gv, const int* __restrict__ channels,
    float* __restrict__ gout)
{
    extern __shared__ float sm[];
    float* Qt = sm;                  // [64 d][132]  Q^T  [d][m]
    float* Kt = Qt + 64 * QT_ST;     // [64 d][68]   K^T  [d][kv], kv swizzled
    float* Vs = Kt + 64 * KV_ST;     // [64 kv][68]  V    [kv][d], d swizzled
    float* Pt = Vs + 64 * KV_ST;     // [64 kv][132] P^T  [kv][m]

    const int h   = blockIdx.y;
    const int tid = threadIdx.x;
    const int tx  = tid & 7;         // kv cols tx*8..+7 / out dims tx*8..+7
    const int ty  = tid >> 3;        // q rows ty*8..+7 (0..15)
    const int sA  = swz(tx * 8), sB = swz(tx * 8 + 4);
    const float SCALE = 0.125f * 1.44269504088896f;   // 1/sqrt(64) * log2(e)

    // Map blockIdx.x -> (q0, segment); no block straddles a segment.
    int b = (int)blockIdx.x, seg_s = 0, seg_e = 0, q0 = 0;
    #pragma unroll
    for (int i = 0; i < 4; i++) {
        if (b >= 0) {
            int len = channels[i] * 196;
            int nb = (len + 127) >> 7;
            if (b < nb) { q0 = seg_s + b * 128; seg_e = seg_s + len; b = -1; }
            else        { b -= nb; seg_s += len; }
        }
    }

    // Load Q tile transposed (rows beyond segment end -> zeros)
    #pragma unroll
    for (int it = 0; it < 16; it++) {
        int i = tid + it * 128;
        int r = i >> 4, c4 = i & 15;
        int qr = q0 + r;
        float4 qv = make_float4(0.f, 0.f, 0.f, 0.f);
        if (qr < seg_e)
            qv = *(const float4*)(gq + (size_t)qr * DM + h * 64 + c4 * 4);
        Qt[(c4 * 4 + 0) * QT_ST + r] = qv.x;
        Qt[(c4 * 4 + 1) * QT_ST + r] = qv.y;
        Qt[(c4 * 4 + 2) * QT_ST + r] = qv.z;
        Qt[(c4 * 4 + 3) * QT_ST + r] = qv.w;
    }

    u64t o2[8][4];
    float m_i[8], l_i[8];
    #pragma unroll
    for (int i = 0; i < 8; i++) {
        #pragma unroll
        for (int jp = 0; jp < 4; jp++) o2[i][jp] = 0ULL;
        m_i[i] = -1e30f; l_i[i] = 0.f;
    }

    for (int kv0 = seg_s; kv0 < seg_e; kv0 += 64) {
        __syncthreads();
        // K (transposed, kv-swizzled) + V (natural, d-swizzled)
        #pragma unroll
        for (int it = 0; it < 8; it++) {
            int i = tid + it * 128;
            int r = i >> 4, c4 = i & 15;
            int kr = kv0 + r;
            float4 kx = make_float4(0.f, 0.f, 0.f, 0.f);
            float4 vx = make_float4(0.f, 0.f, 0.f, 0.f);
            if (kr < seg_e) {
                kx = *(const float4*)(gk + (size_t)kr * DM + h * 64 + c4 * 4);
                vx = *(const float4*)(gv + (size_t)kr * DM + h * 64 + c4 * 4);
            }
            int rs = swz(r);
            Kt[(c4 * 4 + 0) * KV_ST + rs] = kx.x;
            Kt[(c4 * 4 + 1) * KV_ST + rs] = kx.y;
            Kt[(c4 * 4 + 2) * KV_ST + rs] = kx.z;
            Kt[(c4 * 4 + 3) * KV_ST + rs] = kx.w;
            *(float4*)&Vs[r * KV_ST + swz(c4 * 4)] = vx;
        }
        __syncthreads();

        // S = Q K^T : 8 rows x 8 cols per thread
        u64t s2[8][4];
        #pragma unroll
        for (int i = 0; i < 8; i++)
            #pragma unroll
            for (int jp = 0; jp < 4; jp++) s2[i][jp] = 0ULL;
        #pragma unroll 8
        for (int kk = 0; kk < 64; kk++) {
            float4 a0 = *(float4*)&Qt[kk * QT_ST + ty * 8];
            float4 a1 = *(float4*)&Qt[kk * QT_ST + ty * 8 + 4];
            ulonglong2 q0v = *(ulonglong2*)&Kt[kk * KV_ST + sA];
            ulonglong2 q1v = *(ulonglong2*)&Kt[kk * KV_ST + sB];
            u64t bp[4] = {q0v.x, q0v.y, q1v.x, q1v.y};
            float av[8] = {a0.x, a0.y, a0.z, a0.w, a1.x, a1.y, a1.z, a1.w};
            #pragma unroll
            for (int i = 0; i < 8; i++) {
                u64t ad = dup2(av[i]);
                #pragma unroll
                for (int jp = 0; jp < 4; jp++)
                    s2[i][jp] = ffma2(ad, bp[jp], s2[i][jp]);
            }
        }

        // Unpack + mask + scale (log2 units)
        bool valid[8];
        #pragma unroll
        for (int j = 0; j < 8; j++)
            valid[j] = (kv0 + tx * 8 + j) < seg_e;

        float s[8][8], mloc[8];
        #pragma unroll
        for (int i = 0; i < 8; i++) {
            #pragma unroll
            for (int jp = 0; jp < 4; jp++) {
                float2 f = upk(s2[i][jp]);
                s[i][jp * 2 + 0] = f.x;
                s[i][jp * 2 + 1] = f.y;
            }
            mloc[i] = -1e30f;
            #pragma unroll
            for (int j = 0; j < 8; j++) {
                s[i][j] = valid[j] ? s[i][j] * SCALE : -1e30f;
                mloc[i] = fmaxf(mloc[i], s[i][j]);
            }
        }
        // Row reductions across the 8 tx-lanes (lane bits 0..2)
        #pragma unroll
        for (int off = 1; off < 8; off <<= 1)
            #pragma unroll
            for (int i = 0; i < 8; i++)
                mloc[i] = fmaxf(mloc[i], __shfl_xor_sync(0xffffffffu, mloc[i], off));

        float alpha[8];
        #pragma unroll
        for (int i = 0; i < 8; i++) {
            float m_new = fmaxf(m_i[i], mloc[i]);
            alpha[i] = exp2f(m_i[i] - m_new);
            m_i[i] = m_new;
        }

        // p = exp2(s - m); store P^T, accumulate row sums
        float lloc[8];
        #pragma unroll
        for (int i = 0; i < 8; i++) lloc[i] = 0.f;
        #pragma unroll
        for (int j = 0; j < 8; j++) {
            float pv[8];
            #pragma unroll
            for (int i = 0; i < 8; i++) {
                float p = exp2f(s[i][j] - m_i[i]);   // invalid: -1e30 -> 0
                pv[i] = p;
                lloc[i] += p;
            }
            *(float4*)&Pt[(tx * 8 + j) * QT_ST + ty * 8] =
                make_float4(pv[0], pv[1], pv[2], pv[3]);
            *(float4*)&Pt[(tx * 8 + j) * QT_ST + ty * 8 + 4] =
                make_float4(pv[4], pv[5], pv[6], pv[7]);
        }
        #pragma unroll
        for (int off = 1; off < 8; off <<= 1)
            #pragma unroll
            for (int i = 0; i < 8; i++)
                lloc[i] += __shfl_xor_sync(0xffffffffu, lloc[i], off);

        #pragma unroll
        for (int i = 0; i < 8; i++) {
            l_i[i] = l_i[i] * alpha[i] + lloc[i];
            u64t ad = dup2(alpha[i]);
            #pragma unroll
            for (int jp = 0; jp < 4; jp++)
                o2[i][jp] = mul2(o2[i][jp], ad);
        }

        __syncthreads();   // Pt visible to all

        // O += P V
        #pragma unroll 8
        for (int kk = 0; kk < 64; kk++) {
            float4 a0 = *(float4*)&Pt[kk * QT_ST + ty * 8];
            float4 a1 = *(float4*)&Pt[kk * QT_ST + ty * 8 + 4];
            ulonglong2 q0v = *(ulonglong2*)&Vs[kk * KV_ST + sA];
            ulonglong2 q1v = *(ulonglong2*)&Vs[kk * KV_ST + sB];
            u64t bp[4] = {q0v.x, q0v.y, q1v.x, q1v.y};
            float av[8] = {a0.x, a0.y, a0.z, a0.w, a1.x, a1.y, a1.z, a1.w};
            #pragma unroll
            for (int i = 0; i < 8; i++) {
                u64t ad = dup2(av[i]);
                #pragma unroll
                for (int jp = 0; jp < 4; jp++)
                    o2[i][jp] = ffma2(ad, bp[jp], o2[i][jp]);
            }
        }
    }

    #pragma unroll
    for (int i = 0; i < 8; i++) {
        int row = q0 + ty * 8 + i;
        if (row < seg_e) {
            float inv = 1.f / l_i[i];
            float2 r0 = upk(o2[i][0]), r1 = upk(o2[i][1]);
            float2 r2 = upk(o2[i][2]), r3 = upk(o2[i][3]);
            *(float4*)&gout[(size_t)row * DM + h * 64 + tx * 8] =
                make_float4(r0.x * inv, r0.y * inv, r1.x * inv, r1.y * inv);
            *(float4*)&gout[(size_t)row * DM + h * 64 + tx * 8 + 4] =
                make_float4(r2.x * inv, r2.y * inv, r3.x * inv, r3.y * inv);
        }
    }
}

// ---------------------------------------------------------------------------
// Launch
// ---------------------------------------------------------------------------
extern "C" void kernel_launch(void* const* d_in, const int* in_sizes, int n_in,
                              void* d_out, int out_size)
{
    const float* xq  = (const float*)d_in[0];
    const float* xk  = (const float*)d_in[1];
    const float* pos = (const float*)d_in[2];
    const int*   ch  = (const int*)  d_in[3];
    const float* Wq  = (const float*)d_in[4];
    const float* bq  = (const float*)d_in[5];
    const float* Wk  = (const float*)d_in[6];
    const float* bk  = (const float*)d_in[7];
    const float* Wv  = (const float*)d_in[8];
    const float* bv  = (const float*)d_in[9];
    const float* Wo  = (const float*)d_in[10];
    const float* bo  = (const float*)d_in[11];
    float* out = (float*)d_out;

    float *q, *k, *v, *ao;
    cudaGetSymbolAddress((void**)&q,  g_q);
    cudaGetSymbolAddress((void**)&k,  g_k);
    cudaGetSymbolAddress((void**)&v,  g_v);
    cudaGetSymbolAddress((void**)&ao, g_ao);

    const size_t attn_smem = ATTN_SMEM_FLOATS * sizeof(float);
    cudaFuncSetAttribute(attn_kernel, cudaFuncAttributeMaxDynamicSharedMemorySize,
                         (int)attn_smem);

    dim3 gqkv(DM / 64, (TTOK + 127) / 128, 3);   // (8, 25, 3)
    gemm_qkv_kernel<<<gqkv, 128>>>(xq, xk, pos, Wq, bq, Wk, bk, Wv, bv, q, k, v);

    // 28 q-blocks = sum ceil(ch_i*196/128) for channels [2,4,6,4] (fixed input)
    attn_kernel<<<dim3(28, 8), 128, attn_smem>>>(q, k, v, ch, ao);

    dim3 gg(DM / 64, (TTOK + 127) / 128);        // (8, 25)
    gemm512_kernel<<<gg, 128>>>(ao, nullptr, Wo, bo, out);
}